// round 15
// baseline (speedup 1.0000x reference)
#include <cuda_runtime.h>
#include <math.h>

#define T_STEPS 512
#define BATCH   128
#define DIM     512
#define HID     512
#define G3      1536

#define NB   128      // scan blocks: 4 batch-groups x 32 col-groups
#define STPB 256
#define WS   516      // padded smem row stride (floats)
#define REDL 33       // reduction inner stride

__device__ float g_xp[(size_t)T_STEPS * BATCH * G3];
__device__ unsigned int g_bar[4 * T_STEPS];

__device__ __forceinline__ void ffma2(unsigned long long& d,
                                      unsigned long long a,
                                      unsigned long long b) {
    asm("fma.rn.f32x2 %0, %1, %2, %0;" : "+l"(d) : "l"(a), "l"(b));
}
__device__ __forceinline__ unsigned long long splat2(float a) {
    unsigned long long d;
    asm("mov.b64 %0, {%1, %1};" : "=l"(d) : "f"(a));
    return d;
}
__device__ __forceinline__ void unpack2(unsigned long long v, float& lo, float& hi) {
    asm("mov.b64 {%0, %1}, %2;" : "=f"(lo), "=f"(hi) : "l"(v));
}

// ---------------------------------------------------------------------------
// Kernel 1: x_proj = X @ W_ih^T + b_ih   (R13 double-buffered version: proven
// ~70us faster than single-buffer. 1 sync/tile, next-tile LDG under compute,
// 2 CTAs/SM.)
// ---------------------------------------------------------------------------
__global__ __launch_bounds__(256, 2) void xproj_kernel(
    const float* __restrict__ X,
    const float* __restrict__ W,
    const float* __restrict__ bias)
{
    __shared__ float Xs[2][16][128];
    __shared__ float Ws2[2][16][128];

    const int m0  = blockIdx.y * 128;
    const int n0  = blockIdx.x * 128;
    const int tid = threadIdx.x;
    const int tx  = tid & 15;
    const int ty  = tid >> 4;

    unsigned long long accp[8][4];
#pragma unroll
    for (int i = 0; i < 8; i++)
#pragma unroll
        for (int j = 0; j < 4; j++) accp[i][j] = 0ULL;

    const float* Xg = X + (size_t)m0 * DIM;
    const float* Wg = W + (size_t)n0 * DIM;

    // staging map: 512 float4 per operand tile, 2 per thread
    const int r0 = tid >> 2,           q0 = (tid & 3);
    const int r1 = (tid + 256) >> 2,   q1 = (tid & 3);

    // prologue: load tile 0
    float4 xa[2], wa[2];
    xa[0] = *(const float4*)(Xg + (size_t)r0 * DIM + q0 * 4);
    xa[1] = *(const float4*)(Xg + (size_t)r1 * DIM + q1 * 4);
    wa[0] = *(const float4*)(Wg + (size_t)r0 * DIM + q0 * 4);
    wa[1] = *(const float4*)(Wg + (size_t)r1 * DIM + q1 * 4);

    for (int it = 0; it < 32; it++) {
        const int buf = it & 1;
        // store staged regs -> smem buf (readers of this buf finished at the
        // sync of iteration it-1; double buffering makes this race-free)
        {
            float* xs = &Xs[buf][0][0];
            float* ws = &Ws2[buf][0][0];
            xs[(q0 * 4 + 0) * 128 + r0] = xa[0].x;
            xs[(q0 * 4 + 1) * 128 + r0] = xa[0].y;
            xs[(q0 * 4 + 2) * 128 + r0] = xa[0].z;
            xs[(q0 * 4 + 3) * 128 + r0] = xa[0].w;
            xs[(q1 * 4 + 0) * 128 + r1] = xa[1].x;
            xs[(q1 * 4 + 1) * 128 + r1] = xa[1].y;
            xs[(q1 * 4 + 2) * 128 + r1] = xa[1].z;
            xs[(q1 * 4 + 3) * 128 + r1] = xa[1].w;
            ws[(q0 * 4 + 0) * 128 + r0] = wa[0].x;
            ws[(q0 * 4 + 1) * 128 + r0] = wa[0].y;
            ws[(q0 * 4 + 2) * 128 + r0] = wa[0].z;
            ws[(q0 * 4 + 3) * 128 + r0] = wa[0].w;
            ws[(q1 * 4 + 0) * 128 + r1] = wa[1].x;
            ws[(q1 * 4 + 1) * 128 + r1] = wa[1].y;
            ws[(q1 * 4 + 2) * 128 + r1] = wa[1].z;
            ws[(q1 * 4 + 3) * 128 + r1] = wa[1].w;
        }
        // issue next tile's loads (latency hides under this tile's compute)
        if (it < 31) {
            const int kt = (it + 1) * 16;
            xa[0] = *(const float4*)(Xg + (size_t)r0 * DIM + kt + q0 * 4);
            xa[1] = *(const float4*)(Xg + (size_t)r1 * DIM + kt + q1 * 4);
            wa[0] = *(const float4*)(Wg + (size_t)r0 * DIM + kt + q0 * 4);
            wa[1] = *(const float4*)(Wg + (size_t)r1 * DIM + kt + q1 * 4);
        }
        __syncthreads();   // buf ready for all

#pragma unroll
        for (int k = 0; k < 16; k++) {
            float a[8];
            *(float4*)&a[0] = *(const float4*)&Xs[buf][k][ty * 4];
            *(float4*)&a[4] = *(const float4*)&Xs[buf][k][ty * 4 + 64];
            ulonglong2 b0 = *(const ulonglong2*)&Ws2[buf][k][tx * 4];
            ulonglong2 b1 = *(const ulonglong2*)&Ws2[buf][k][tx * 4 + 64];
#pragma unroll
            for (int i = 0; i < 8; i++) {
                unsigned long long ai = splat2(a[i]);
                ffma2(accp[i][0], ai, b0.x);
                ffma2(accp[i][1], ai, b0.y);
                ffma2(accp[i][2], ai, b1.x);
                ffma2(accp[i][3], ai, b1.y);
            }
        }
    }

    float4 blo = *(const float4*)(bias + n0 + tx * 4);
    float4 bhi = *(const float4*)(bias + n0 + 64 + tx * 4);
#pragma unroll
    for (int i = 0; i < 8; i++) {
        int m = m0 + ty * 4 + ((i < 4) ? i : (64 + i - 4));
        float c[8];
        unpack2(accp[i][0], c[0], c[1]);
        unpack2(accp[i][1], c[2], c[3]);
        unpack2(accp[i][2], c[4], c[5]);
        unpack2(accp[i][3], c[6], c[7]);
        float4 v0, v1;
        v0.x = c[0] + blo.x; v0.y = c[1] + blo.y;
        v0.z = c[2] + blo.z; v0.w = c[3] + blo.w;
        v1.x = c[4] + bhi.x; v1.y = c[5] + bhi.y;
        v1.z = c[6] + bhi.z; v1.w = c[7] + bhi.w;
        *(float4*)&g_xp[(size_t)m * G3 + n0 + tx * 4]      = v0;
        *(float4*)&g_xp[(size_t)m * G3 + n0 + 64 + tx * 4] = v1;
    }
}

// ---------------------------------------------------------------------------
// Kernel 2: persistent GRU scan — R14 champion, byte-identical.
// Split-K staged pipeline: warp ks covers k in {ks*32..+32} and
// {256+ks*32..+32}; all 16 LDGs issued up front, chunk-B store waits hidden
// under GEMM-A.
// ---------------------------------------------------------------------------
__global__ __launch_bounds__(STPB, 1) void scan_kernel(
    const float* __restrict__ Whh,
    const float* __restrict__ bhh,
    float* __restrict__ out)
{
    extern __shared__ float smem[];
    float* wsh = smem;                     // 48 rows x WS
    float* hsh = smem + 48 * WS;           // 32 rows x WS
    float* red = smem + 80 * WS;           // [3][16][8][REDL]

    const int tid  = threadIdx.x;
    const int bk   = blockIdx.x;
    const int bg   = bk >> 5;
    const int cg   = bk & 31;
    const int ks   = tid >> 5;
    const int lane = tid & 31;
    const int bgrp = lane >> 2;
    const int cgrp = lane & 3;
    const int kA   = ks * 32;              // chunk A slice
    const int kB   = 256 + ks * 32;        // chunk B slice

    for (int i = tid; i < 48 * 128; i += STPB) {
        int row = i >> 7, q = i & 127;
        int g = row >> 4, lc = row & 15;
        *(float4*)&wsh[row * WS + q * 4] =
            *(const float4*)(Whh + (size_t)(g * 512 + cg * 16 + lc) * 512 + q * 4);
    }

    const int co  = tid >> 4;
    const int bo  = (tid & 15) * 2;
    const int cGo = cg * 16 + co;
    const int bGo = bg * 32 + bo;
    float bh[3];
#pragma unroll
    for (int g = 0; g < 3; g++) bh[g] = bhh[g * 512 + cGo];
    __syncthreads();

    float hprev[2] = {0.f, 0.f};

    const int srow4 = tid >> 6;            // 0..3
    const int scolh = (tid & 63) * 4;      // 0..252

    for (int t = 0; t < T_STEPS; t++) {
        float xgv[2][3];
        {
            const float* xb = g_xp + ((size_t)t * BATCH + bGo) * G3 + cGo;
#pragma unroll
            for (int j = 0; j < 2; j++)
#pragma unroll
                for (int g = 0; g < 3; g++)
                    xgv[j][g] = xb[(size_t)j * G3 + g * 512];
        }

        if (t > 0) {
            const float* hp = out + (size_t)(t - 1) * (BATCH * HID)
                                  + (size_t)(bg * 32) * HID;
            // issue ALL loads up front (A first, then B)
            float4 pfA[8], pfB[8];
#pragma unroll
            for (int j = 0; j < 8; j++) {
                int row = j * 4 + srow4;
                pfA[j] = *(const float4*)(hp + (size_t)row * HID + scolh);
            }
#pragma unroll
            for (int j = 0; j < 8; j++) {
                int row = j * 4 + srow4;
                pfB[j] = *(const float4*)(hp + (size_t)row * HID + 256 + scolh);
            }
            // store chunk A, sync
#pragma unroll
            for (int j = 0; j < 8; j++) {
                int row = j * 4 + srow4;
                *(float4*)&hsh[row * WS + scolh] = pfA[j];
            }
            __syncthreads();

            unsigned long long acc[4][4][3];
#pragma unroll
            for (int bi = 0; bi < 4; bi++)
#pragma unroll
                for (int ci = 0; ci < 4; ci++)
#pragma unroll
                    for (int g = 0; g < 3; g++) acc[bi][ci][g] = 0ULL;

            // GEMM over chunk A (32 k's) while chunk B loads land
#pragma unroll 2
            for (int kk = 0; kk < 32; kk += 4) {
                const int k = kA + kk;
                ulonglong2 h2[4];
#pragma unroll
                for (int bi = 0; bi < 4; bi++)
                    h2[bi] = *(const ulonglong2*)&hsh[(bgrp + 8 * bi) * WS + k];
#pragma unroll
                for (int g = 0; g < 3; g++)
#pragma unroll
                    for (int ci = 0; ci < 4; ci++) {
                        ulonglong2 w = *(const ulonglong2*)
                            &wsh[(g * 16 + cgrp + 4 * ci) * WS + k];
#pragma unroll
                        for (int bi = 0; bi < 4; bi++) {
                            ffma2(acc[bi][ci][g], h2[bi].x, w.x);
                            ffma2(acc[bi][ci][g], h2[bi].y, w.y);
                        }
                    }
            }

            // store chunk B (loads have had GEMM-A time to land), sync
#pragma unroll
            for (int j = 0; j < 8; j++) {
                int row = j * 4 + srow4;
                *(float4*)&hsh[row * WS + 256 + scolh] = pfB[j];
            }
            __syncthreads();

            // GEMM over chunk B
#pragma unroll 2
            for (int kk = 0; kk < 32; kk += 4) {
                const int k = kB + kk;
                ulonglong2 h2[4];
#pragma unroll
                for (int bi = 0; bi < 4; bi++)
                    h2[bi] = *(const ulonglong2*)&hsh[(bgrp + 8 * bi) * WS + k];
#pragma unroll
                for (int g = 0; g < 3; g++)
#pragma unroll
                    for (int ci = 0; ci < 4; ci++) {
                        ulonglong2 w = *(const ulonglong2*)
                            &wsh[(g * 16 + cgrp + 4 * ci) * WS + k];
#pragma unroll
                        for (int bi = 0; bi < 4; bi++) {
                            ffma2(acc[bi][ci][g], h2[bi].x, w.x);
                            ffma2(acc[bi][ci][g], h2[bi].y, w.y);
                        }
                    }
            }

            // publish partials: red[g][c][ks][b]
#pragma unroll
            for (int bi = 0; bi < 4; bi++)
#pragma unroll
                for (int ci = 0; ci < 4; ci++)
#pragma unroll
                    for (int g = 0; g < 3; g++) {
                        float lo, hi;
                        unpack2(acc[bi][ci][g], lo, hi);
                        int b = bgrp + 8 * bi;
                        int c = cgrp + 4 * ci;
                        red[((g * 16 + c) * 8 + ks) * REDL + b] = lo + hi;
                    }
            __syncthreads();
        }

        {
            float* ob = out + (size_t)t * (BATCH * HID);
#pragma unroll
            for (int j = 0; j < 2; j++) {
                float s[3] = {0.f, 0.f, 0.f};
                if (t > 0) {
#pragma unroll
                    for (int g = 0; g < 3; g++) {
                        float a = 0.f;
#pragma unroll
                        for (int k8 = 0; k8 < 8; k8++)
                            a += red[((g * 16 + co) * 8 + k8) * REDL + bo + j];
                        s[g] = a;
                    }
                }
                float hr = s[0] + bh[0];
                float hz = s[1] + bh[1];
                float hn = s[2] + bh[2];
                float r = 1.f / (1.f + __expf(-(xgv[j][0] + hr)));
                float z = 1.f / (1.f + __expf(-(xgv[j][1] + hz)));
                float n = tanhf(xgv[j][2] + r * hn);
                float hv = (1.f - z) * n + z * hprev[j];
                hprev[j] = hv;
                ob[(size_t)(bGo + j) * HID + cGo] = hv;
            }
        }

        if (t < T_STEPS - 1) {
            __threadfence();
            __syncthreads();
            if (tid == 0) {
                unsigned* ctr = &g_bar[bg * T_STEPS + t];
                unsigned prev = atomicAdd(ctr, 1u);
                if (prev + 1u < 32u) {
                    while (*((volatile unsigned*)ctr) < 32u) { }
                }
                if (cg == 0 && t > 0) g_bar[bg * T_STEPS + t - 1] = 0u;
                __threadfence();
            }
            __syncthreads();
        }
    }

    __syncthreads();
    if (tid == 0) {
        __threadfence();
        unsigned d = atomicAdd(&g_bar[bg * T_STEPS + T_STEPS - 1], 1u);
        if (d + 1u == 32u) {
            g_bar[bg * T_STEPS + T_STEPS - 2] = 0u;
            g_bar[bg * T_STEPS + T_STEPS - 1] = 0u;
            __threadfence();
        }
    }
}

// ---------------------------------------------------------------------------
extern "C" void kernel_launch(void* const* d_in, const int* in_sizes, int n_in,
                              void* d_out, int out_size)
{
    const float* inputs = (const float*)d_in[0];
    const float* W_ih   = (const float*)d_in[1];
    const float* W_hh   = (const float*)d_in[2];
    const float* b_ih   = (const float*)d_in[3];
    const float* b_hh   = (const float*)d_in[4];
    float* out = (float*)d_out;

    (void)in_sizes; (void)n_in; (void)out_size;

    const int dyn_smem =
        (80 * WS + 3 * 16 * 8 * REDL) * (int)sizeof(float);   // ~215 KB
    static int smem_set = 0;
    if (!smem_set) {
        cudaFuncSetAttribute(scan_kernel,
                             cudaFuncAttributeMaxDynamicSharedMemorySize, dyn_smem);
        smem_set = 1;
    }

    dim3 g1(G3 / 128, (T_STEPS * BATCH) / 128, 1);
    xproj_kernel<<<g1, 256>>>(inputs, W_ih, b_ih);
    scan_kernel<<<NB, STPB, dyn_smem>>>(W_hh, b_hh, out);
}

// round 16
// speedup vs baseline: 1.0418x; 1.0418x over previous
#include <cuda_runtime.h>
#include <math.h>

#define T_STEPS 512
#define BATCH   128
#define DIM     512
#define HID     512
#define G3      1536

#define NB   128      // scan blocks: 4 batch-groups x 32 col-groups
#define STPB 256
#define WS   516      // padded smem row stride (floats)
#define REDL 33       // reduction inner stride

__device__ float g_xp[(size_t)T_STEPS * BATCH * G3];
__device__ unsigned int g_bar[4 * T_STEPS];

__device__ __forceinline__ void ffma2(unsigned long long& d,
                                      unsigned long long a,
                                      unsigned long long b) {
    asm("fma.rn.f32x2 %0, %1, %2, %0;" : "+l"(d) : "l"(a), "l"(b));
}
__device__ __forceinline__ unsigned long long splat2(float a) {
    unsigned long long d;
    asm("mov.b64 %0, {%1, %1};" : "=l"(d) : "f"(a));
    return d;
}
__device__ __forceinline__ void unpack2(unsigned long long v, float& lo, float& hi) {
    asm("mov.b64 {%0, %1}, %2;" : "=f"(lo), "=f"(hi) : "l"(v));
}
__device__ __forceinline__ unsigned atom_add_acqrel_gpu(unsigned* p, unsigned v) {
    unsigned old;
    asm volatile("atom.add.acq_rel.gpu.u32 %0, [%1], %2;"
                 : "=r"(old) : "l"(p), "r"(v) : "memory");
    return old;
}
__device__ __forceinline__ unsigned ld_acquire_gpu(const unsigned* p) {
    unsigned v;
    asm volatile("ld.acquire.gpu.u32 %0, [%1];" : "=r"(v) : "l"(p) : "memory");
    return v;
}

// ---------------------------------------------------------------------------
// Kernel 1: x_proj = X @ W_ih^T + b_ih  (R14 single-buffer champion version —
// the db/2-CTA variant raises power and depresses the scan's DVFS clock)
// ---------------------------------------------------------------------------
__global__ __launch_bounds__(256) void xproj_kernel(
    const float* __restrict__ X,
    const float* __restrict__ W,
    const float* __restrict__ bias)
{
    __shared__ float Xs[16][128];
    __shared__ float Ws2[16][128];

    const int m0  = blockIdx.y * 128;
    const int n0  = blockIdx.x * 128;
    const int tid = threadIdx.x;
    const int tx  = tid & 15;
    const int ty  = tid >> 4;

    unsigned long long accp[8][4];
#pragma unroll
    for (int i = 0; i < 8; i++)
#pragma unroll
        for (int j = 0; j < 4; j++) accp[i][j] = 0ULL;

    const float* Xg = X + (size_t)m0 * DIM;
    const float* Wg = W + (size_t)n0 * DIM;

    for (int kt = 0; kt < DIM; kt += 16) {
        float4 xa[2], wa[2];
#pragma unroll
        for (int i = 0; i < 2; i++) {
            int idx = tid + i * 256;
            int row = idx >> 2, kq = idx & 3;
            xa[i] = *(const float4*)(Xg + (size_t)row * DIM + kt + kq * 4);
            wa[i] = *(const float4*)(Wg + (size_t)row * DIM + kt + kq * 4);
        }
        __syncthreads();
#pragma unroll
        for (int i = 0; i < 2; i++) {
            int idx = tid + i * 256;
            int row = idx >> 2, kq = idx & 3;
            Xs[kq * 4 + 0][row] = xa[i].x;  Xs[kq * 4 + 1][row] = xa[i].y;
            Xs[kq * 4 + 2][row] = xa[i].z;  Xs[kq * 4 + 3][row] = xa[i].w;
            Ws2[kq * 4 + 0][row] = wa[i].x; Ws2[kq * 4 + 1][row] = wa[i].y;
            Ws2[kq * 4 + 2][row] = wa[i].z; Ws2[kq * 4 + 3][row] = wa[i].w;
        }
        __syncthreads();

#pragma unroll
        for (int k = 0; k < 16; k++) {
            float a[8];
            *(float4*)&a[0] = *(const float4*)&Xs[k][ty * 4];
            *(float4*)&a[4] = *(const float4*)&Xs[k][ty * 4 + 64];
            ulonglong2 b0 = *(const ulonglong2*)&Ws2[k][tx * 4];
            ulonglong2 b1 = *(const ulonglong2*)&Ws2[k][tx * 4 + 64];
#pragma unroll
            for (int i = 0; i < 8; i++) {
                unsigned long long ai = splat2(a[i]);
                ffma2(accp[i][0], ai, b0.x);
                ffma2(accp[i][1], ai, b0.y);
                ffma2(accp[i][2], ai, b1.x);
                ffma2(accp[i][3], ai, b1.y);
            }
        }
    }

    float4 blo = *(const float4*)(bias + n0 + tx * 4);
    float4 bhi = *(const float4*)(bias + n0 + 64 + tx * 4);
#pragma unroll
    for (int i = 0; i < 8; i++) {
        int m = m0 + ty * 4 + ((i < 4) ? i : (64 + i - 4));
        float c[8];
        unpack2(accp[i][0], c[0], c[1]);
        unpack2(accp[i][1], c[2], c[3]);
        unpack2(accp[i][2], c[4], c[5]);
        unpack2(accp[i][3], c[6], c[7]);
        float4 v0, v1;
        v0.x = c[0] + blo.x; v0.y = c[1] + blo.y;
        v0.z = c[2] + blo.z; v0.w = c[3] + blo.w;
        v1.x = c[4] + bhi.x; v1.y = c[5] + bhi.y;
        v1.z = c[6] + bhi.z; v1.w = c[7] + bhi.w;
        *(float4*)&g_xp[(size_t)m * G3 + n0 + tx * 4]      = v0;
        *(float4*)&g_xp[(size_t)m * G3 + n0 + 64 + tx * 4] = v1;
    }
}

// ---------------------------------------------------------------------------
// Kernel 2: persistent GRU scan — R14 champion with release/acquire barrier
// (per-thread __threadfence removed; tid0 signals with atom.add.acq_rel.gpu,
// spinners use ld.acquire.gpu; syncthreads supplies intra-block HB).
// ---------------------------------------------------------------------------
__global__ __launch_bounds__(STPB, 1) void scan_kernel(
    const float* __restrict__ Whh,
    const float* __restrict__ bhh,
    float* __restrict__ out)
{
    extern __shared__ float smem[];
    float* wsh = smem;                     // 48 rows x WS
    float* hsh = smem + 48 * WS;           // 32 rows x WS
    float* red = smem + 80 * WS;           // [3][16][8][REDL]

    const int tid  = threadIdx.x;
    const int bk   = blockIdx.x;
    const int bg   = bk >> 5;
    const int cg   = bk & 31;
    const int ks   = tid >> 5;
    const int lane = tid & 31;
    const int bgrp = lane >> 2;
    const int cgrp = lane & 3;
    const int kA   = ks * 32;              // chunk A slice
    const int kB   = 256 + ks * 32;        // chunk B slice

    for (int i = tid; i < 48 * 128; i += STPB) {
        int row = i >> 7, q = i & 127;
        int g = row >> 4, lc = row & 15;
        *(float4*)&wsh[row * WS + q * 4] =
            *(const float4*)(Whh + (size_t)(g * 512 + cg * 16 + lc) * 512 + q * 4);
    }

    const int co  = tid >> 4;
    const int bo  = (tid & 15) * 2;
    const int cGo = cg * 16 + co;
    const int bGo = bg * 32 + bo;
    float bh[3];
#pragma unroll
    for (int g = 0; g < 3; g++) bh[g] = bhh[g * 512 + cGo];
    __syncthreads();

    float hprev[2] = {0.f, 0.f};

    const int srow4 = tid >> 6;            // 0..3
    const int scolh = (tid & 63) * 4;      // 0..252

    for (int t = 0; t < T_STEPS; t++) {
        float xgv[2][3];
        {
            const float* xb = g_xp + ((size_t)t * BATCH + bGo) * G3 + cGo;
#pragma unroll
            for (int j = 0; j < 2; j++)
#pragma unroll
                for (int g = 0; g < 3; g++)
                    xgv[j][g] = xb[(size_t)j * G3 + g * 512];
        }

        if (t > 0) {
            const float* hp = out + (size_t)(t - 1) * (BATCH * HID)
                                  + (size_t)(bg * 32) * HID;
            // issue ALL loads up front (A first, then B)
            float4 pfA[8], pfB[8];
#pragma unroll
            for (int j = 0; j < 8; j++) {
                int row = j * 4 + srow4;
                pfA[j] = *(const float4*)(hp + (size_t)row * HID + scolh);
            }
#pragma unroll
            for (int j = 0; j < 8; j++) {
                int row = j * 4 + srow4;
                pfB[j] = *(const float4*)(hp + (size_t)row * HID + 256 + scolh);
            }
            // store chunk A, sync
#pragma unroll
            for (int j = 0; j < 8; j++) {
                int row = j * 4 + srow4;
                *(float4*)&hsh[row * WS + scolh] = pfA[j];
            }
            __syncthreads();

            unsigned long long acc[4][4][3];
#pragma unroll
            for (int bi = 0; bi < 4; bi++)
#pragma unroll
                for (int ci = 0; ci < 4; ci++)
#pragma unroll
                    for (int g = 0; g < 3; g++) acc[bi][ci][g] = 0ULL;

            // GEMM over chunk A (32 k's) while chunk B loads land
#pragma unroll 2
            for (int kk = 0; kk < 32; kk += 4) {
                const int k = kA + kk;
                ulonglong2 h2[4];
#pragma unroll
                for (int bi = 0; bi < 4; bi++)
                    h2[bi] = *(const ulonglong2*)&hsh[(bgrp + 8 * bi) * WS + k];
#pragma unroll
                for (int g = 0; g < 3; g++)
#pragma unroll
                    for (int ci = 0; ci < 4; ci++) {
                        ulonglong2 w = *(const ulonglong2*)
                            &wsh[(g * 16 + cgrp + 4 * ci) * WS + k];
#pragma unroll
                        for (int bi = 0; bi < 4; bi++) {
                            ffma2(acc[bi][ci][g], h2[bi].x, w.x);
                            ffma2(acc[bi][ci][g], h2[bi].y, w.y);
                        }
                    }
            }

            // store chunk B (loads have had GEMM-A time to land), sync
#pragma unroll
            for (int j = 0; j < 8; j++) {
                int row = j * 4 + srow4;
                *(float4*)&hsh[row * WS + 256 + scolh] = pfB[j];
            }
            __syncthreads();

            // GEMM over chunk B
#pragma unroll 2
            for (int kk = 0; kk < 32; kk += 4) {
                const int k = kB + kk;
                ulonglong2 h2[4];
#pragma unroll
                for (int bi = 0; bi < 4; bi++)
                    h2[bi] = *(const ulonglong2*)&hsh[(bgrp + 8 * bi) * WS + k];
#pragma unroll
                for (int g = 0; g < 3; g++)
#pragma unroll
                    for (int ci = 0; ci < 4; ci++) {
                        ulonglong2 w = *(const ulonglong2*)
                            &wsh[(g * 16 + cgrp + 4 * ci) * WS + k];
#pragma unroll
                        for (int bi = 0; bi < 4; bi++) {
                            ffma2(acc[bi][ci][g], h2[bi].x, w.x);
                            ffma2(acc[bi][ci][g], h2[bi].y, w.y);
                        }
                    }
            }

            // publish partials: red[g][c][ks][b]
#pragma unroll
            for (int bi = 0; bi < 4; bi++)
#pragma unroll
                for (int ci = 0; ci < 4; ci++)
#pragma unroll
                    for (int g = 0; g < 3; g++) {
                        float lo, hi;
                        unpack2(acc[bi][ci][g], lo, hi);
                        int b = bgrp + 8 * bi;
                        int c = cgrp + 4 * ci;
                        red[((g * 16 + c) * 8 + ks) * REDL + b] = lo + hi;
                    }
            __syncthreads();
        }

        {
            float* ob = out + (size_t)t * (BATCH * HID);
#pragma unroll
            for (int j = 0; j < 2; j++) {
                float s[3] = {0.f, 0.f, 0.f};
                if (t > 0) {
#pragma unroll
                    for (int g = 0; g < 3; g++) {
                        float a = 0.f;
#pragma unroll
                        for (int k8 = 0; k8 < 8; k8++)
                            a += red[((g * 16 + co) * 8 + k8) * REDL + bo + j];
                        s[g] = a;
                    }
                }
                float hr = s[0] + bh[0];
                float hz = s[1] + bh[1];
                float hn = s[2] + bh[2];
                float r = 1.f / (1.f + __expf(-(xgv[j][0] + hr)));
                float z = 1.f / (1.f + __expf(-(xgv[j][1] + hz)));
                float n = tanhf(xgv[j][2] + r * hn);
                float hv = (1.f - z) * n + z * hprev[j];
                hprev[j] = hv;
                ob[(size_t)(bGo + j) * HID + cGo] = hv;
            }
        }

        // release/acquire group barrier (no per-thread threadfence):
        //   STG(plain) -> syncthreads(HB) -> tid0 atom.add.acq_rel(release
        //   publishes block's stores) ; spinners ld.acquire ; post-sync
        //   extends the acquire to all threads before they read h[t].
        if (t < T_STEPS - 1) {
            __syncthreads();
            if (tid == 0) {
                unsigned* ctr = &g_bar[bg * T_STEPS + t];
                unsigned prev = atom_add_acqrel_gpu(ctr, 1u);
                if (prev + 1u < 32u) {
                    while (ld_acquire_gpu(ctr) < 32u) { }
                }
                if (cg == 0 && t > 0) g_bar[bg * T_STEPS + t - 1] = 0u;
            }
            __syncthreads();
        }
    }

    // cleanup: leave all counters zero for graph replay (cold path — keep
    // conservative fences)
    __syncthreads();
    if (tid == 0) {
        __threadfence();
        unsigned d = atomicAdd(&g_bar[bg * T_STEPS + T_STEPS - 1], 1u);
        if (d + 1u == 32u) {
            g_bar[bg * T_STEPS + T_STEPS - 2] = 0u;
            g_bar[bg * T_STEPS + T_STEPS - 1] = 0u;
            __threadfence();
        }
    }
}

// ---------------------------------------------------------------------------
extern "C" void kernel_launch(void* const* d_in, const int* in_sizes, int n_in,
                              void* d_out, int out_size)
{
    const float* inputs = (const float*)d_in[0];
    const float* W_ih   = (const float*)d_in[1];
    const float* W_hh   = (const float*)d_in[2];
    const float* b_ih   = (const float*)d_in[3];
    const float* b_hh   = (const float*)d_in[4];
    float* out = (float*)d_out;

    (void)in_sizes; (void)n_in; (void)out_size;

    const int dyn_smem =
        (80 * WS + 3 * 16 * 8 * REDL) * (int)sizeof(float);   // ~215 KB
    static int smem_set = 0;
    if (!smem_set) {
        cudaFuncSetAttribute(scan_kernel,
                             cudaFuncAttributeMaxDynamicSharedMemorySize, dyn_smem);
        smem_set = 1;
    }

    dim3 g1(G3 / 128, (T_STEPS * BATCH) / 128, 1);
    xproj_kernel<<<g1, 256>>>(inputs, W_ih, b_ih);
    scan_kernel<<<NB, STPB, dyn_smem>>>(W_hh, b_hh, out);
}